// round 13
// baseline (speedup 1.0000x reference)
#include <cuda_runtime.h>
#include <cstdint>

#define T_STEPS 512
#define BATCH   256
#define DIN     256
#define HID     128
#define GATES   512   // 4*HID, gate order i,f,g,o

// Scratch: allocation-free rule => __device__ globals.
__device__ float g_xg[(size_t)T_STEPS * BATCH * GATES];  // x@W_ih^T + b_ih + b_hh

// ---------------- packed f32x2 helpers (FFMA2: 2 MACs/instr) ----------------
__device__ __forceinline__ unsigned long long dup2(float x) {
    unsigned long long r; asm("mov.b64 %0, {%1, %1};" : "=l"(r) : "f"(x)); return r;
}
__device__ __forceinline__ void up2(unsigned long long v, float& lo, float& hi) {
    asm("mov.b64 {%0, %1}, %2;" : "=f"(lo), "=f"(hi) : "l"(v));
}
__device__ __forceinline__ unsigned long long fma2(unsigned long long a, unsigned long long b,
                                                   unsigned long long c) {
    unsigned long long d;
    asm("fma.rn.f32x2 %0, %1, %2, %3;" : "=l"(d) : "l"(a), "l"(b), "l"(c));
    return d;
}
__device__ __forceinline__ float sigm_f(float x) { return 1.0f / (1.0f + __expf(-x)); }
__device__ __forceinline__ float tanh_f(float x) { return 2.0f / (1.0f + __expf(-2.0f * x)) - 1.0f; }

// ============================================================================
// Kernel 1: x_gates GEMM — UNCHANGED (measured ~570us, ~88% of f32x2 roofline).
// ============================================================================
__global__ void __launch_bounds__(256) xg_gemm(const float* __restrict__ X,
                                               const float* __restrict__ Wih,
                                               const float* __restrict__ bih,
                                               const float* __restrict__ bhh)
{
    __shared__ __align__(16) float As[2][16][132];
    __shared__ __align__(16) float Bs[2][16][132];

    const int tid = threadIdx.x;
    const int m0  = blockIdx.y * 128;
    const int n0  = blockIdx.x * 128;
    const int tx  = tid & 15;
    const int ty  = tid >> 4;
    const int row = tid >> 2;
    const int kq  = tid & 3;

    const float* Ap = X   + (size_t)(m0 + row) * DIN + kq * 4;
    const float* Bp = Wih + (size_t)(n0 + row) * DIN + kq * 4;

    float4 ra0 = *(const float4*)(Ap);
    float4 ra1 = *(const float4*)(Ap + 64 * DIN);
    float4 rb0 = *(const float4*)(Bp);
    float4 rb1 = *(const float4*)(Bp + 64 * DIN);

    unsigned long long acc[8][4];
#pragma unroll
    for (int i = 0; i < 8; ++i)
#pragma unroll
        for (int j = 0; j < 4; ++j) acc[i][j] = 0ULL;

    int buf = 0;
#pragma unroll 1
    for (int kt = 0; kt < 16; ++kt) {
#pragma unroll
        for (int e = 0; e < 4; ++e) {
            As[buf][kq*4+e][row]    = ((const float*)&ra0)[e];
            As[buf][kq*4+e][row+64] = ((const float*)&ra1)[e];
            Bs[buf][kq*4+e][row]    = ((const float*)&rb0)[e];
            Bs[buf][kq*4+e][row+64] = ((const float*)&rb1)[e];
        }
        __syncthreads();
        if (kt < 15) {
            ra0 = *(const float4*)(Ap + (kt+1)*16);
            ra1 = *(const float4*)(Ap + 64*DIN + (kt+1)*16);
            rb0 = *(const float4*)(Bp + (kt+1)*16);
            rb1 = *(const float4*)(Bp + 64*DIN + (kt+1)*16);
        }
#pragma unroll
        for (int k = 0; k < 16; ++k) {
            float4 a0 = *(const float4*)&As[buf][k][ty*4];
            float4 a1 = *(const float4*)&As[buf][k][64 + ty*4];
            ulonglong2 b0 = *(const ulonglong2*)&Bs[buf][k][tx*4];
            ulonglong2 b1 = *(const ulonglong2*)&Bs[buf][k][64 + tx*4];
            float am[8] = {a0.x,a0.y,a0.z,a0.w,a1.x,a1.y,a1.z,a1.w};
            unsigned long long bp[4] = {b0.x, b0.y, b1.x, b1.y};
#pragma unroll
            for (int i = 0; i < 8; ++i) {
                unsigned long long ad = dup2(am[i]);
#pragma unroll
                for (int j = 0; j < 4; ++j) acc[i][j] = fma2(ad, bp[j], acc[i][j]);
            }
        }
        buf ^= 1;
    }

    float b_lo[4], b_hi[4];
#pragma unroll
    for (int j = 0; j < 4; ++j) {
        b_lo[j] = bih[n0 + tx*4 + j]      + bhh[n0 + tx*4 + j];
        b_hi[j] = bih[n0 + 64 + tx*4 + j] + bhh[n0 + 64 + tx*4 + j];
    }
#pragma unroll
    for (int i = 0; i < 8; ++i) {
        int m = m0 + ((i < 4) ? (ty*4 + i) : (64 + ty*4 + i - 4));
        float v[8];
        up2(acc[i][0], v[0], v[1]);
        up2(acc[i][1], v[2], v[3]);
        up2(acc[i][2], v[4], v[5]);
        up2(acc[i][3], v[6], v[7]);
        float* dst = g_xg + (size_t)m * GATES + n0;
        *(float4*)(dst + tx*4)      = make_float4(v[0]+b_lo[0], v[1]+b_lo[1], v[2]+b_lo[2], v[3]+b_lo[3]);
        *(float4*)(dst + 64 + tx*4) = make_float4(v[4]+b_hi[0], v[5]+b_hi[1], v[6]+b_hi[2], v[7]+b_hi[3]);
    }
}

// ============================================================================
// Kernel 2: register-resident-W recurrence, v2.
// Changes vs R12: (a) per-step cluster barrier -> warp-aggregated mbarrier
// rendezvous (count=32: 16 local + 16 remote warp arrivals; parity = t&1);
// (b) kh pair reduction via shfl_xor(1): pre traffic halved, gather 8->4 LDS.
// ============================================================================
#define HSTR 136

__global__ void __launch_bounds__(512) __cluster_dims__(2, 1, 1)
lstm_rec(const float* __restrict__ Whh, const float* __restrict__ h0,
         const float* __restrict__ c0,  const float* __restrict__ fcw,
         const float* __restrict__ fcb, float* __restrict__ out)
{
    __shared__ __align__(16) float hb[2 * 4 * HSTR];     // [parity][b][HSTR]
    __shared__ __align__(16) float pre[4 * 64 * 4];      // word = q*256 + jj*4 + b
    __shared__ __align__(8) unsigned long long mbar;

    const int tid = threadIdx.x;
    const int q   = tid >> 7;          // gate 0..3
    const int jj  = (tid >> 1) & 63;   // output within slice
    const int kh  = tid & 1;           // k half
    uint32_t rank;
    asm("mov.u32 %0, %%cluster_ctarank;" : "=r"(rank));
    const uint32_t peer = rank ^ 1u;
    const int bbase = (blockIdx.x >> 1) * 4;

    const uint32_t mb_l = (uint32_t)__cvta_generic_to_shared(&mbar);
    uint32_t mb_r;
    asm volatile("mapa.shared::cluster.u32 %0, %1, %2;" : "=r"(mb_r) : "r"(mb_l), "r"(peer));

    if (tid == 0) {
        asm volatile("mbarrier.init.shared.b64 [%0], 32;" :: "r"(mb_l) : "memory");
    }

    // Resident W: (gate row, k-half) -> 32 u64 registers.
    unsigned long long Wp[32];
    {
        const float* wr = Whh + (size_t)(q * 128 + (int)rank * 64 + jj) * HID + kh * 64;
#pragma unroll
        for (int i = 0; i < 16; ++i) {
            ulonglong2 v = *(const ulonglong2*)(wr + i * 4);
            Wp[2*i]   = v.x;
            Wp[2*i+1] = v.y;
        }
    }

    // init h (parity 0), slot-mapped: slot(k) = k + (k>>6)*4
    for (int idx = tid; idx < 4 * HID; idx += 512) {
        int b_ = idx >> 7, k = idx & 127;
        hb[b_ * HSTR + k + ((k >> 6) << 2)] = h0[(size_t)(bbase + b_) * HID + k];
    }

    // update role (tid < 256): (ujj, ub) owns c and the gate nonlinearity
    const int ujj = tid >> 2, ub = tid & 3;
    const int ujg = (int)rank * 64 + ujj;
    float c = 0.0f;
    const float* xgp = nullptr;
    float nx0 = 0.f, nx1 = 0.f, nx2 = 0.f, nx3 = 0.f;
    if (tid < 256) {
        c = c0[(size_t)(bbase + ub) * HID + ujg];
        xgp = g_xg + (size_t)(bbase + ub) * GATES + ujg;
        nx0 = xgp[0]; nx1 = xgp[128]; nx2 = xgp[256]; nx3 = xgp[384];
    }
    __syncthreads();
    // one-time cluster rendezvous: mbarrier init + h init visible cluster-wide
    asm volatile("barrier.cluster.arrive.aligned;" ::: "memory");
    asm volatile("barrier.cluster.wait.aligned;"   ::: "memory");

    int p = 0;
#pragma unroll 1
    for (int t = 0; t < T_STEPS; ++t) {
        // GEMV partials for 4 batches over this thread's 64-k half.
        const float* hp = hb + (size_t)p * 4 * HSTR + kh * 68;
        unsigned long long ae0=0,ao0=0,ae1=0,ao1=0,ae2=0,ao2=0,ae3=0,ao3=0;
#pragma unroll
        for (int i = 0; i < 16; ++i) {
            ulonglong2 hv0 = *(const ulonglong2*)(hp + 0*HSTR + i*4);
            ulonglong2 hv1 = *(const ulonglong2*)(hp + 1*HSTR + i*4);
            ulonglong2 hv2 = *(const ulonglong2*)(hp + 2*HSTR + i*4);
            ulonglong2 hv3 = *(const ulonglong2*)(hp + 3*HSTR + i*4);
            ae0 = fma2(Wp[2*i], hv0.x, ae0); ao0 = fma2(Wp[2*i+1], hv0.y, ao0);
            ae1 = fma2(Wp[2*i], hv1.x, ae1); ao1 = fma2(Wp[2*i+1], hv1.y, ao1);
            ae2 = fma2(Wp[2*i], hv2.x, ae2); ao2 = fma2(Wp[2*i+1], hv2.y, ao2);
            ae3 = fma2(Wp[2*i], hv3.x, ae3); ao3 = fma2(Wp[2*i+1], hv3.y, ao3);
        }
        float4 pv;
        { float l,h,l2,h2; up2(ae0,l,h); up2(ao0,l2,h2); pv.x = (l+h)+(l2+h2); }
        { float l,h,l2,h2; up2(ae1,l,h); up2(ao1,l2,h2); pv.y = (l+h)+(l2+h2); }
        { float l,h,l2,h2; up2(ae2,l,h); up2(ao2,l2,h2); pv.z = (l+h)+(l2+h2); }
        { float l,h,l2,h2; up2(ae3,l,h); up2(ao3,l2,h2); pv.w = (l+h)+(l2+h2); }
        // combine kh halves in-register (partner lane = tid^1)
        pv.x += __shfl_xor_sync(0xFFFFFFFFu, pv.x, 1);
        pv.y += __shfl_xor_sync(0xFFFFFFFFu, pv.y, 1);
        pv.z += __shfl_xor_sync(0xFFFFFFFFu, pv.z, 1);
        pv.w += __shfl_xor_sync(0xFFFFFFFFu, pv.w, 1);
        if (kh == 0) *(float4*)(pre + q * 256 + jj * 4) = pv;
        __syncthreads();

        if (tid < 256) {
            float gi = nx0 + pre[tid];
            float gf = nx1 + pre[256  + tid];
            float gg = nx2 + pre[512  + tid];
            float go = nx3 + pre[768  + tid];
            if (t + 1 < T_STEPS) {                     // prefetch next step's xg
                const float* pn = xgp + (size_t)(t + 1) * (BATCH * GATES);
                nx0 = pn[0]; nx1 = pn[128]; nx2 = pn[256]; nx3 = pn[384];
            }
            float ig = sigm_f(gi), fg = sigm_f(gf), gt = tanh_f(gg), og = sigm_f(go);
            c = fg * c + ig * gt;
            float h = og * tanh_f(c);

            int slot = ujg + ((ujg >> 6) << 2);
            float* dst = hb + ((size_t)(p ^ 1) * 4 + ub) * HSTR + slot;
            *dst = h;
            uint32_t la = (uint32_t)__cvta_generic_to_shared(dst);
            uint32_t ra;
            asm volatile("mapa.shared::cluster.u32 %0, %1, %2;" : "=r"(ra) : "r"(la), "r"(peer));
            asm volatile("st.shared::cluster.f32 [%0], %1;" :: "r"(ra), "f"(h) : "memory");
        }

        // cluster rendezvous: each warp arrives (elected lane) on BOTH CTAs'
        // mbarriers after its work; all threads wait on the local one.
        __syncwarp();
        if ((tid & 31) == 0) {
            asm volatile("mbarrier.arrive.release.cluster.shared::cta.b64 _, [%0];"
                         :: "r"(mb_l) : "memory");
            asm volatile("mbarrier.arrive.release.cluster.shared::cluster.b64 _, [%0];"
                         :: "r"(mb_r) : "memory");
        }
        {
            uint32_t par = (uint32_t)(t & 1);
            uint32_t done;
            asm volatile(
                "{\n\t.reg .pred p;\n\t"
                "mbarrier.try_wait.parity.acquire.cluster.shared::cta.b64 p, [%1], %2;\n\t"
                "selp.b32 %0, 1, 0, p;\n\t}"
                : "=r"(done) : "r"(mb_l), "r"(par) : "memory");
            if (!done) {
                asm volatile(
                    "{\n\t.reg .pred P1;\n\t"
                    "WL_%=:\n\t"
                    "mbarrier.try_wait.parity.acquire.cluster.shared::cta.b64 P1, [%0], %1, 0x989680;\n\t"
                    "@P1 bra.uni WD_%=;\n\t"
                    "bra.uni WL_%=;\n\t"
                    "WD_%=:\n\t}"
                    :: "r"(mb_l), "r"(par) : "memory");
            }
        }
        p ^= 1;
    }

    // FC head: rank 0, warp 0 — warp-parallel dots over slot-mapped final h.
    if (rank == 0 && tid < 32) {
        for (int b_ = 0; b_ < 4; ++b_) {
            const float* hr = hb + ((size_t)p * 4 + b_) * HSTR;
            float acc = 0.0f;
#pragma unroll
            for (int kk = 0; kk < 4; ++kk) {
                int k = tid + kk * 32;
                acc += hr[k + ((k >> 6) << 2)] * fcw[k];
            }
#pragma unroll
            for (int off = 16; off > 0; off >>= 1)
                acc += __shfl_xor_sync(0xFFFFFFFFu, acc, off);
            if (tid == 0) out[bbase + b_] = acc + fcb[0];
        }
    }
}

// ============================================================================
extern "C" void kernel_launch(void* const* d_in, const int* in_sizes, int n_in,
                              void* d_out, int out_size) {
    const float* x   = (const float*)d_in[0];
    const float* h0  = (const float*)d_in[1];
    const float* c0  = (const float*)d_in[2];
    const float* Wih = (const float*)d_in[3];
    const float* Whh = (const float*)d_in[4];
    const float* bih = (const float*)d_in[5];
    const float* bhh = (const float*)d_in[6];
    const float* fcw = (const float*)d_in[7];
    const float* fcb = (const float*)d_in[8];
    float* out = (float*)d_out;
    (void)in_sizes; (void)n_in; (void)out_size;

    dim3 g1(GATES / 128, (T_STEPS * BATCH) / 128);   // (4, 1024)
    xg_gemm<<<g1, 256>>>(x, Wih, bih, bhh);
    lstm_rec<<<128, 512>>>(Whh, h0, c0, fcw, fcb, out);
}